// round 5
// baseline (speedup 1.0000x reference)
#include <cuda_runtime.h>
#include <cuda_fp16.h>
#include <cstdint>

#define MAXN 50000
#define MAXE 800000
#define FIN 256
#define FH  64
#define FOUT 40
#define KSTEPS 10
#define SCAN_TPB 256
#define MAXBLK 256
#define TILE_N 32
#define XS_STRIDE 260   // 256 + 4 pad: breaks LDS bank aliasing of 1KB rows

// packed fp32x2 helpers (Blackwell dual fp32)
#define PACK2(out, lo, hi) asm("mov.b64 %0, {%1, %2};" : "=l"(out) : "f"(lo), "f"(hi))
#define UNPACK2(lo, hi, in) asm("mov.b64 {%0, %1}, %2;" : "=f"(lo), "=f"(hi) : "l"(in))
#define FMA2(d, a, b, c) asm("fma.rn.f32x2 %0, %1, %2, %3;" : "=l"(d) : "l"(a), "l"(b), "l"(c))

// ---------------- static device scratch ----------------
__device__ int     g_deg[MAXN];
__device__ float   g_dinv[MAXN];
__device__ int     g_ptr[MAXN + 1];
__device__ int     g_cursor[MAXN];
__device__ int     g_part[MAXBLK];
__device__ __align__(16) int2    g_csr[MAXE];
// feature pairing: slot p of a node = features (2p, 2p+1)
__device__ __align__(16) float2  g_h0[MAXN * 32];
__device__ __align__(16) __half2 g_hA[MAXN * 32];
__device__ __align__(16) __half2 g_hB[MAXN * 32];
__device__ __align__(16) float   g_mlp1[MAXN * FH];

__device__ __forceinline__ int clampN(int v, int n) {
    v = v < 0 ? 0 : v;
    return v >= n ? n - 1 : v;
}

// ---------------- graph preprocessing ----------------
__global__ void init_kernel(int n) {
    int i = blockIdx.x * blockDim.x + threadIdx.x;
    if (i < n) { g_deg[i] = 1; g_cursor[i] = 0; }   // self loop
}

__global__ void hist_kernel(const int* __restrict__ ei, int E, int n) {
    int e = blockIdx.x * blockDim.x + threadIdx.x;
    if (e < E) atomicAdd(&g_deg[clampN(ei[E + e], n)], 1);
}

// scan stage A: per-block sums of (deg-1); also computes dinv
__global__ void scanA_kernel(int n) {
    int i = blockIdx.x * blockDim.x + threadIdx.x;
    int lane = threadIdx.x & 31, wid = threadIdx.x >> 5;
    __shared__ int ws[SCAN_TPB / 32];
    int d = (i < n) ? g_deg[i] : 1;
    if (i < n) g_dinv[i] = rsqrtf((float)d);
    int v = (i < n) ? (d - 1) : 0;
    #pragma unroll
    for (int o = 16; o > 0; o >>= 1) v += __shfl_down_sync(0xFFFFFFFFu, v, o);
    if (lane == 0) ws[wid] = v;
    __syncthreads();
    if (wid == 0) {
        int s = (lane < SCAN_TPB / 32) ? ws[lane] : 0;
        #pragma unroll
        for (int o = 16; o > 0; o >>= 1) s += __shfl_down_sync(0xFFFFFFFFu, s, o);
        if (lane == 0) g_part[blockIdx.x] = s;
    }
}

// scan stage B: exclusive scan of block partials (single block)
__global__ void scanB_kernel(int nblocks, int n) {
    int tid = threadIdx.x, lane = tid & 31, wid = tid >> 5;
    __shared__ int ws[8];
    int v = (tid < nblocks) ? g_part[tid] : 0;
    int x = v;
    #pragma unroll
    for (int o = 1; o < 32; o <<= 1) {
        int y = __shfl_up_sync(0xFFFFFFFFu, x, o);
        if (lane >= o) x += y;
    }
    if (lane == 31) ws[wid] = x;
    __syncthreads();
    if (wid == 0) {
        int s = (lane < 8) ? ws[lane] : 0;
        #pragma unroll
        for (int o = 1; o < 8; o <<= 1) {
            int y = __shfl_up_sync(0xFFFFFFFFu, s, o);
            if (lane >= o) s += y;
        }
        ws[lane] = s;
    }
    __syncthreads();
    int incl = x + (wid > 0 ? ws[wid - 1] : 0);
    if (tid < nblocks) g_part[tid] = incl - v;
    if (tid == nblocks - 1) g_ptr[n] = incl;
}

// scan stage C: intra-block exclusive scan + block offset -> g_ptr
__global__ void scanC_kernel(int n) {
    int i = blockIdx.x * blockDim.x + threadIdx.x;
    int lane = threadIdx.x & 31, wid = threadIdx.x >> 5;
    __shared__ int ws[SCAN_TPB / 32];
    int v = (i < n) ? (g_deg[i] - 1) : 0;
    int x = v;
    #pragma unroll
    for (int o = 1; o < 32; o <<= 1) {
        int y = __shfl_up_sync(0xFFFFFFFFu, x, o);
        if (lane >= o) x += y;
    }
    if (lane == 31) ws[wid] = x;
    __syncthreads();
    if (wid == 0) {
        int s = (lane < SCAN_TPB / 32) ? ws[lane] : 0;
        #pragma unroll
        for (int o = 1; o < SCAN_TPB / 32; o <<= 1) {
            int y = __shfl_up_sync(0xFFFFFFFFu, s, o);
            if (lane >= o) s += y;
        }
        ws[lane] = s;
    }
    __syncthreads();
    int incl = x + (wid > 0 ? ws[wid - 1] : 0);
    if (i < n) g_ptr[i] = incl - v + g_part[blockIdx.x];
}

__global__ void scatter_kernel(const int* __restrict__ ei, int E, int n) {
    int e = blockIdx.x * blockDim.x + threadIdx.x;
    if (e < E) {
        int r = clampN(ei[e], n);
        int c = clampN(ei[E + e], n);
        int pos = g_ptr[c] + atomicAdd(&g_cursor[c], 1);
        float w = g_dinv[r] * g_dinv[c];
        g_csr[pos] = make_int2(r, __float_as_int(w));
    }
}

// ---------------- mlp1: block-tiled GEMM, 32 nodes/block, f32x2 ----------------
__global__ void mlp1_kernel(const float* __restrict__ x,
                            const float* __restrict__ W1,
                            const float* __restrict__ b1, int n) {
    __shared__ float xs[TILE_N * XS_STRIDE];
    int tid = threadIdx.x;
    int base = blockIdx.x * TILE_N;

    // stage x tile (float4 coalesced)
    for (int idx = tid; idx < TILE_N * (FIN / 4); idx += 256) {
        int node = idx / (FIN / 4);
        int c4 = idx % (FIN / 4);
        float4 v = make_float4(0.f, 0.f, 0.f, 0.f);
        if (base + node < n)
            v = ((const float4*)x)[(size_t)(base + node) * (FIN / 4) + c4];
        *(float4*)&xs[node * XS_STRIDE + c4 * 4] = v;
    }
    __syncthreads();

    int node = tid >> 3;          // 0..31
    int col  = (tid & 7) * 8;     // 8 outputs per thread

    unsigned long long acc0, acc1, acc2, acc3;
    PACK2(acc0, b1[col + 0], b1[col + 1]);
    PACK2(acc1, b1[col + 2], b1[col + 3]);
    PACK2(acc2, b1[col + 4], b1[col + 5]);
    PACK2(acc3, b1[col + 6], b1[col + 7]);

    #pragma unroll 4
    for (int k = 0; k < FIN; k += 4) {
        float4 xv = *(const float4*)&xs[node * XS_STRIDE + k];
        #pragma unroll
        for (int kk = 0; kk < 4; kk++) {
            float xk = (kk == 0) ? xv.x : (kk == 1) ? xv.y : (kk == 2) ? xv.z : xv.w;
            unsigned long long xk2;
            PACK2(xk2, xk, xk);
            const unsigned long long* wp =
                (const unsigned long long*)&W1[(k + kk) * FH + col];
            FMA2(acc0, xk2, wp[0], acc0);
            FMA2(acc1, xk2, wp[1], acc1);
            FMA2(acc2, xk2, wp[2], acc2);
            FMA2(acc3, xk2, wp[3], acc3);
        }
    }

    int gnode = base + node;
    if (gnode < n) {
        float r[8];
        UNPACK2(r[0], r[1], acc0);
        UNPACK2(r[2], r[3], acc1);
        UNPACK2(r[4], r[5], acc2);
        UNPACK2(r[6], r[7], acc3);
        #pragma unroll
        for (int i = 0; i < 8; i++) r[i] = fmaxf(r[i], 0.0f);
        float4* dst = (float4*)&g_mlp1[(size_t)gnode * FH + col];
        dst[0] = make_float4(r[0], r[1], r[2], r[3]);
        dst[1] = make_float4(r[4], r[5], r[6], r[7]);
    }
}

// ---------------- mlp2: warp/node shuffle GEMM, f32x2 ----------------
__global__ void mlp2_kernel(const float* __restrict__ W2,
                            const float* __restrict__ b2, int n) {
    int warp = (blockIdx.x * blockDim.x + threadIdx.x) >> 5;
    int lane = threadIdx.x & 31;
    if (warp >= n) return;
    const float* hr = g_mlp1 + (size_t)warp * FH;
    unsigned long long acc;
    PACK2(acc, b2[2 * lane], b2[2 * lane + 1]);
    #pragma unroll
    for (int kb = 0; kb < FH; kb += 32) {
        float hv = hr[kb + lane];
        #pragma unroll
        for (int j = 0; j < 32; j++) {
            float hk = __shfl_sync(0xFFFFFFFFu, hv, j);
            unsigned long long hk2, wv;
            PACK2(hk2, hk, hk);
            wv = *(const unsigned long long*)&W2[(kb + j) * FH + 2 * lane];
            FMA2(acc, hk2, wv, acc);
        }
    }
    float a0, a1;
    UNPACK2(a0, a1, acc);
    g_hA[warp * 32 + lane] = __floats2half2_rn(a0, a1);   // features (2l, 2l+1)
    g_h0[warp * 32 + lane] = make_float2(a0, a1);
}

// ---------------- APPNP step (optionally fused decode) ----------------
template <int SRC_A, int DECODE>
__global__ void prop_kernel(const float* __restrict__ Wf,
                            const float* __restrict__ bf,
                            float* __restrict__ out, int n) {
    int node = (blockIdx.x * blockDim.x + threadIdx.x) >> 5;
    int lane = threadIdx.x & 31;
    if (node >= n) return;
    const __half2* __restrict__ hin  = SRC_A ? g_hA : g_hB;
    __half2*       __restrict__ hout = SRC_A ? g_hB : g_hA;

    int start = g_ptr[node];
    int end   = g_ptr[node + 1];

    float di = g_dinv[node];
    float wself = di * di;
    float2 hv = __half22float2(hin[node * 32 + lane]);
    float ax = wself * hv.x;
    float ay = wself * hv.y;

    int e = start;
    for (; e + 8 <= end; e += 8) {
        int2 s0 = g_csr[e + 0], s1 = g_csr[e + 1], s2 = g_csr[e + 2], s3 = g_csr[e + 3];
        int2 s4 = g_csr[e + 4], s5 = g_csr[e + 5], s6 = g_csr[e + 6], s7 = g_csr[e + 7];
        __half2 v0 = hin[s0.x * 32 + lane], v1 = hin[s1.x * 32 + lane];
        __half2 v2 = hin[s2.x * 32 + lane], v3 = hin[s3.x * 32 + lane];
        __half2 v4 = hin[s4.x * 32 + lane], v5 = hin[s5.x * 32 + lane];
        __half2 v6 = hin[s6.x * 32 + lane], v7 = hin[s7.x * 32 + lane];
        float2 f0 = __half22float2(v0), f1 = __half22float2(v1);
        float2 f2 = __half22float2(v2), f3 = __half22float2(v3);
        float2 f4 = __half22float2(v4), f5 = __half22float2(v5);
        float2 f6 = __half22float2(v6), f7 = __half22float2(v7);
        float w0 = __int_as_float(s0.y), w1 = __int_as_float(s1.y);
        float w2 = __int_as_float(s2.y), w3 = __int_as_float(s3.y);
        float w4 = __int_as_float(s4.y), w5 = __int_as_float(s5.y);
        float w6 = __int_as_float(s6.y), w7 = __int_as_float(s7.y);
        ax = fmaf(w0, f0.x, ax); ay = fmaf(w0, f0.y, ay);
        ax = fmaf(w1, f1.x, ax); ay = fmaf(w1, f1.y, ay);
        ax = fmaf(w2, f2.x, ax); ay = fmaf(w2, f2.y, ay);
        ax = fmaf(w3, f3.x, ax); ay = fmaf(w3, f3.y, ay);
        ax = fmaf(w4, f4.x, ax); ay = fmaf(w4, f4.y, ay);
        ax = fmaf(w5, f5.x, ax); ay = fmaf(w5, f5.y, ay);
        ax = fmaf(w6, f6.x, ax); ay = fmaf(w6, f6.y, ay);
        ax = fmaf(w7, f7.x, ax); ay = fmaf(w7, f7.y, ay);
    }
    for (; e + 4 <= end; e += 4) {
        int2 s0 = g_csr[e + 0], s1 = g_csr[e + 1], s2 = g_csr[e + 2], s3 = g_csr[e + 3];
        __half2 v0 = hin[s0.x * 32 + lane], v1 = hin[s1.x * 32 + lane];
        __half2 v2 = hin[s2.x * 32 + lane], v3 = hin[s3.x * 32 + lane];
        float2 f0 = __half22float2(v0), f1 = __half22float2(v1);
        float2 f2 = __half22float2(v2), f3 = __half22float2(v3);
        float w0 = __int_as_float(s0.y), w1 = __int_as_float(s1.y);
        float w2 = __int_as_float(s2.y), w3 = __int_as_float(s3.y);
        ax = fmaf(w0, f0.x, ax); ay = fmaf(w0, f0.y, ay);
        ax = fmaf(w1, f1.x, ax); ay = fmaf(w1, f1.y, ay);
        ax = fmaf(w2, f2.x, ax); ay = fmaf(w2, f2.y, ay);
        ax = fmaf(w3, f3.x, ax); ay = fmaf(w3, f3.y, ay);
    }
    for (; e < end; e++) {
        int2 s = g_csr[e];
        float2 f = __half22float2(hin[s.x * 32 + lane]);
        float w = __int_as_float(s.y);
        ax = fmaf(w, f.x, ax);
        ay = fmaf(w, f.y, ay);
    }

    float2 t = g_h0[node * 32 + lane];
    float ox = 0.9f * ax + 0.1f * t.x;     // features (2l, 2l+1), fp32
    float oy = 0.9f * ay + 0.1f * t.y;

    if (!DECODE) {
        hout[node * 32 + lane] = __floats2half2_rn(ox, oy);
    } else {
        // fused decode: out[node] = h @ Wf + bf (h in registers, fp32)
        float acc0 = bf[lane];
        float acc1 = (lane < FOUT - 32) ? bf[lane + 32] : 0.0f;
        #pragma unroll
        for (int j = 0; j < 32; j++) {
            float hx = __shfl_sync(0xFFFFFFFFu, ox, j);   // feature 2j
            float hy = __shfl_sync(0xFFFFFFFFu, oy, j);   // feature 2j+1
            acc0 = fmaf(hx, Wf[(2 * j) * FOUT + lane], acc0);
            acc0 = fmaf(hy, Wf[(2 * j + 1) * FOUT + lane], acc0);
            if (lane < FOUT - 32) {
                acc1 = fmaf(hx, Wf[(2 * j) * FOUT + lane + 32], acc1);
                acc1 = fmaf(hy, Wf[(2 * j + 1) * FOUT + lane + 32], acc1);
            }
        }
        out[(size_t)node * FOUT + lane] = acc0;
        if (lane < FOUT - 32)
            out[(size_t)node * FOUT + lane + 32] = acc1;
    }
}

// ---------------- launch ----------------
extern "C" void kernel_launch(void* const* d_in, const int* in_sizes, int n_in,
                              void* d_out, int out_size) {
    const float* x  = (const float*)d_in[0];
    const int*   ei = (const int*)d_in[1];
    const float* W1 = (const float*)d_in[2];
    const float* b1 = (const float*)d_in[3];
    const float* W2 = (const float*)d_in[4];
    const float* b2 = (const float*)d_in[5];
    const float* Wf = (const float*)d_in[6];
    const float* bf = (const float*)d_in[7];
    float* out = (float*)d_out;

    int N = in_sizes[0] / FIN;
    int E = in_sizes[1] / 2;
    if (N > MAXN) N = MAXN;
    if (E > MAXE) E = MAXE;

    int tpb = 256;
    int nblk = (N + SCAN_TPB - 1) / SCAN_TPB;

    init_kernel<<<(N + tpb - 1) / tpb, tpb>>>(N);
    hist_kernel<<<(E + tpb - 1) / tpb, tpb>>>(ei, E, N);
    scanA_kernel<<<nblk, SCAN_TPB>>>(N);          // also computes dinv
    scanB_kernel<<<1, MAXBLK>>>(nblk, N);
    scanC_kernel<<<nblk, SCAN_TPB>>>(N);
    scatter_kernel<<<(E + tpb - 1) / tpb, tpb>>>(ei, E, N);

    mlp1_kernel<<<(N + TILE_N - 1) / TILE_N, 256>>>(x, W1, b1, N);
    int wblocks = (N + 7) / 8;
    mlp2_kernel<<<wblocks, tpb>>>(W2, b2, N);

    // steps 0..8 normal (t even reads A writes B; t odd reads B writes A)
    for (int t = 0; t < KSTEPS - 1; t++) {
        if ((t & 1) == 0) prop_kernel<1, 0><<<wblocks, tpb>>>(Wf, bf, out, N);
        else              prop_kernel<0, 0><<<wblocks, tpb>>>(Wf, bf, out, N);
    }
    // step 9 (odd, reads B) with fused decode
    prop_kernel<0, 1><<<wblocks, tpb>>>(Wf, bf, out, N);
}

// round 6
// speedup vs baseline: 1.1514x; 1.1514x over previous
#include <cuda_runtime.h>
#include <cuda_fp16.h>
#include <cstdint>

#define MAXN 50000
#define MAXE 800000
#define FIN 256
#define FH  64
#define FOUT 40
#define KSTEPS 10
#define SCAN_TPB 256
#define MAXBLK 256

// packed fp32x2 helpers (Blackwell dual fp32)
#define PACK2(out, lo, hi) asm("mov.b64 %0, {%1, %2};" : "=l"(out) : "f"(lo), "f"(hi))
#define UNPACK2(lo, hi, in) asm("mov.b64 {%0, %1}, %2;" : "=f"(lo), "=f"(hi) : "l"(in))
#define FMA2(d, a, b, c) asm("fma.rn.f32x2 %0, %1, %2, %3;" : "=l"(d) : "l"(a), "l"(b), "l"(c))

// ---------------- static device scratch ----------------
__device__ int     g_deg[MAXN];
__device__ float   g_dinv[MAXN];
__device__ int     g_ptr[MAXN + 1];
__device__ int     g_cursor[MAXN];
__device__ int     g_part[MAXBLK];
__device__ __align__(16) int2    g_csr[MAXE];
// feature pairing: slot p of a node = features (2p, 2p+1)
__device__ __align__(16) float2  g_h0[MAXN * 32];
__device__ __align__(16) __half2 g_hA[MAXN * 32];
__device__ __align__(16) __half2 g_hB[MAXN * 32];
__device__ __align__(16) float   g_mlp1[MAXN * FH];

__device__ __forceinline__ int clampN(int v, int n) {
    v = v < 0 ? 0 : v;
    return v >= n ? n - 1 : v;
}

// ---------------- graph preprocessing ----------------
__global__ void init_kernel(int n) {
    int i = blockIdx.x * blockDim.x + threadIdx.x;
    if (i < n) { g_deg[i] = 1; g_cursor[i] = 0; }   // self loop
}

__global__ void hist_kernel(const int* __restrict__ ei, int E, int n) {
    int e = blockIdx.x * blockDim.x + threadIdx.x;
    if (e < E) atomicAdd(&g_deg[clampN(ei[E + e], n)], 1);
}

// scan stage A: per-block sums of (deg-1); also computes dinv
__global__ void scanA_kernel(int n) {
    int i = blockIdx.x * blockDim.x + threadIdx.x;
    int lane = threadIdx.x & 31, wid = threadIdx.x >> 5;
    __shared__ int ws[SCAN_TPB / 32];
    int d = (i < n) ? g_deg[i] : 1;
    if (i < n) g_dinv[i] = rsqrtf((float)d);
    int v = (i < n) ? (d - 1) : 0;
    #pragma unroll
    for (int o = 16; o > 0; o >>= 1) v += __shfl_down_sync(0xFFFFFFFFu, v, o);
    if (lane == 0) ws[wid] = v;
    __syncthreads();
    if (wid == 0) {
        int s = (lane < SCAN_TPB / 32) ? ws[lane] : 0;
        #pragma unroll
        for (int o = 16; o > 0; o >>= 1) s += __shfl_down_sync(0xFFFFFFFFu, s, o);
        if (lane == 0) g_part[blockIdx.x] = s;
    }
}

// scan stage B: exclusive scan of block partials (single block)
__global__ void scanB_kernel(int nblocks, int n) {
    int tid = threadIdx.x, lane = tid & 31, wid = tid >> 5;
    __shared__ int ws[8];
    int v = (tid < nblocks) ? g_part[tid] : 0;
    int x = v;
    #pragma unroll
    for (int o = 1; o < 32; o <<= 1) {
        int y = __shfl_up_sync(0xFFFFFFFFu, x, o);
        if (lane >= o) x += y;
    }
    if (lane == 31) ws[wid] = x;
    __syncthreads();
    if (wid == 0) {
        int s = (lane < 8) ? ws[lane] : 0;
        #pragma unroll
        for (int o = 1; o < 8; o <<= 1) {
            int y = __shfl_up_sync(0xFFFFFFFFu, s, o);
            if (lane >= o) s += y;
        }
        ws[lane] = s;
    }
    __syncthreads();
    int incl = x + (wid > 0 ? ws[wid - 1] : 0);
    if (tid < nblocks) g_part[tid] = incl - v;
    if (tid == nblocks - 1) g_ptr[n] = incl;
}

// scan stage C: intra-block exclusive scan + block offset -> g_ptr
__global__ void scanC_kernel(int n) {
    int i = blockIdx.x * blockDim.x + threadIdx.x;
    int lane = threadIdx.x & 31, wid = threadIdx.x >> 5;
    __shared__ int ws[SCAN_TPB / 32];
    int v = (i < n) ? (g_deg[i] - 1) : 0;
    int x = v;
    #pragma unroll
    for (int o = 1; o < 32; o <<= 1) {
        int y = __shfl_up_sync(0xFFFFFFFFu, x, o);
        if (lane >= o) x += y;
    }
    if (lane == 31) ws[wid] = x;
    __syncthreads();
    if (wid == 0) {
        int s = (lane < SCAN_TPB / 32) ? ws[lane] : 0;
        #pragma unroll
        for (int o = 1; o < SCAN_TPB / 32; o <<= 1) {
            int y = __shfl_up_sync(0xFFFFFFFFu, s, o);
            if (lane >= o) s += y;
        }
        ws[lane] = s;
    }
    __syncthreads();
    int incl = x + (wid > 0 ? ws[wid - 1] : 0);
    if (i < n) g_ptr[i] = incl - v + g_part[blockIdx.x];
}

__global__ void scatter_kernel(const int* __restrict__ ei, int E, int n) {
    int e = blockIdx.x * blockDim.x + threadIdx.x;
    if (e < E) {
        int r = clampN(ei[e], n);
        int c = clampN(ei[E + e], n);
        int pos = g_ptr[c] + atomicAdd(&g_cursor[c], 1);
        float w = g_dinv[r] * g_dinv[c];
        g_csr[pos] = make_int2(r, __float_as_int(w));
    }
}

// ---------------- MLP encode: warp/node, lane owns features (2l, 2l+1), f32x2 ----
__global__ void mlp1_kernel(const float* __restrict__ x,
                            const float* __restrict__ W1,
                            const float* __restrict__ b1, int n) {
    int warp = (blockIdx.x * blockDim.x + threadIdx.x) >> 5;
    int lane = threadIdx.x & 31;
    if (warp >= n) return;
    const float* xr = x + (size_t)warp * FIN;
    unsigned long long acc;
    PACK2(acc, b1[2 * lane], b1[2 * lane + 1]);
    for (int kb = 0; kb < FIN; kb += 32) {
        float xv = xr[kb + lane];
        #pragma unroll
        for (int j = 0; j < 32; j++) {
            float xk = __shfl_sync(0xFFFFFFFFu, xv, j);
            unsigned long long xk2, wv;
            PACK2(xk2, xk, xk);
            wv = *(const unsigned long long*)&W1[(kb + j) * FH + 2 * lane];
            FMA2(acc, xk2, wv, acc);
        }
    }
    float a0, a1;
    UNPACK2(a0, a1, acc);
    *(float2*)&g_mlp1[warp * FH + 2 * lane] =
        make_float2(fmaxf(a0, 0.0f), fmaxf(a1, 0.0f));
}

__global__ void mlp2_kernel(const float* __restrict__ W2,
                            const float* __restrict__ b2, int n) {
    int warp = (blockIdx.x * blockDim.x + threadIdx.x) >> 5;
    int lane = threadIdx.x & 31;
    if (warp >= n) return;
    const float* hr = g_mlp1 + (size_t)warp * FH;
    unsigned long long acc;
    PACK2(acc, b2[2 * lane], b2[2 * lane + 1]);
    #pragma unroll
    for (int kb = 0; kb < FH; kb += 32) {
        float hv = hr[kb + lane];
        #pragma unroll
        for (int j = 0; j < 32; j++) {
            float hk = __shfl_sync(0xFFFFFFFFu, hv, j);
            unsigned long long hk2, wv;
            PACK2(hk2, hk, hk);
            wv = *(const unsigned long long*)&W2[(kb + j) * FH + 2 * lane];
            FMA2(acc, hk2, wv, acc);
        }
    }
    float a0, a1;
    UNPACK2(a0, a1, acc);
    g_hA[warp * 32 + lane] = __floats2half2_rn(a0, a1);   // features (2l, 2l+1)
    g_h0[warp * 32 + lane] = make_float2(a0, a1);
}

// ---------------- APPNP step: warp/node, uniform CSR loads, unroll x4 ----------
template <int SRC_A, int DECODE>
__global__ void prop_kernel(const float* __restrict__ Wf,
                            const float* __restrict__ bf,
                            float* __restrict__ out, int n) {
    int node = (blockIdx.x * blockDim.x + threadIdx.x) >> 5;
    int lane = threadIdx.x & 31;
    if (node >= n) return;
    const __half2* __restrict__ hin  = SRC_A ? g_hA : g_hB;
    __half2*       __restrict__ hout = SRC_A ? g_hB : g_hA;

    int start = g_ptr[node];
    int end   = g_ptr[node + 1];

    float di = g_dinv[node];
    float wself = di * di;
    float2 hv = __half22float2(hin[node * 32 + lane]);
    float ax = wself * hv.x;
    float ay = wself * hv.y;

    int e = start;
    for (; e + 4 <= end; e += 4) {
        int2 s0 = g_csr[e + 0];          // uniform (broadcast) loads
        int2 s1 = g_csr[e + 1];
        int2 s2 = g_csr[e + 2];
        int2 s3 = g_csr[e + 3];
        __half2 v0 = hin[s0.x * 32 + lane];  // 4 independent gathers in flight
        __half2 v1 = hin[s1.x * 32 + lane];
        __half2 v2 = hin[s2.x * 32 + lane];
        __half2 v3 = hin[s3.x * 32 + lane];
        float2 f0 = __half22float2(v0);
        float2 f1 = __half22float2(v1);
        float2 f2 = __half22float2(v2);
        float2 f3 = __half22float2(v3);
        float w0 = __int_as_float(s0.y);
        float w1 = __int_as_float(s1.y);
        float w2 = __int_as_float(s2.y);
        float w3 = __int_as_float(s3.y);
        ax = fmaf(w0, f0.x, ax);  ay = fmaf(w0, f0.y, ay);
        ax = fmaf(w1, f1.x, ax);  ay = fmaf(w1, f1.y, ay);
        ax = fmaf(w2, f2.x, ax);  ay = fmaf(w2, f2.y, ay);
        ax = fmaf(w3, f3.x, ax);  ay = fmaf(w3, f3.y, ay);
    }
    for (; e < end; e++) {
        int2 s = g_csr[e];
        float2 f = __half22float2(hin[s.x * 32 + lane]);
        float w = __int_as_float(s.y);
        ax = fmaf(w, f.x, ax);
        ay = fmaf(w, f.y, ay);
    }

    float2 t = g_h0[node * 32 + lane];
    float ox = 0.9f * ax + 0.1f * t.x;     // features (2l, 2l+1), fp32
    float oy = 0.9f * ay + 0.1f * t.y;

    if (!DECODE) {
        hout[node * 32 + lane] = __floats2half2_rn(ox, oy);
    } else {
        // fused decode: out[node] = h @ Wf + bf (h in registers, fp32)
        float acc0 = bf[lane];
        float acc1 = (lane < FOUT - 32) ? bf[lane + 32] : 0.0f;
        #pragma unroll
        for (int j = 0; j < 32; j++) {
            float hx = __shfl_sync(0xFFFFFFFFu, ox, j);   // feature 2j
            float hy = __shfl_sync(0xFFFFFFFFu, oy, j);   // feature 2j+1
            acc0 = fmaf(hx, Wf[(2 * j) * FOUT + lane], acc0);
            acc0 = fmaf(hy, Wf[(2 * j + 1) * FOUT + lane], acc0);
            if (lane < FOUT - 32) {
                acc1 = fmaf(hx, Wf[(2 * j) * FOUT + lane + 32], acc1);
                acc1 = fmaf(hy, Wf[(2 * j + 1) * FOUT + lane + 32], acc1);
            }
        }
        out[(size_t)node * FOUT + lane] = acc0;
        if (lane < FOUT - 32)
            out[(size_t)node * FOUT + lane + 32] = acc1;
    }
}

// ---------------- launch ----------------
extern "C" void kernel_launch(void* const* d_in, const int* in_sizes, int n_in,
                              void* d_out, int out_size) {
    const float* x  = (const float*)d_in[0];
    const int*   ei = (const int*)d_in[1];
    const float* W1 = (const float*)d_in[2];
    const float* b1 = (const float*)d_in[3];
    const float* W2 = (const float*)d_in[4];
    const float* b2 = (const float*)d_in[5];
    const float* Wf = (const float*)d_in[6];
    const float* bf = (const float*)d_in[7];
    float* out = (float*)d_out;

    int N = in_sizes[0] / FIN;
    int E = in_sizes[1] / 2;
    if (N > MAXN) N = MAXN;
    if (E > MAXE) E = MAXE;

    int tpb = 256;
    int nblk = (N + SCAN_TPB - 1) / SCAN_TPB;

    init_kernel<<<(N + tpb - 1) / tpb, tpb>>>(N);
    hist_kernel<<<(E + tpb - 1) / tpb, tpb>>>(ei, E, N);
    scanA_kernel<<<nblk, SCAN_TPB>>>(N);          // also computes dinv
    scanB_kernel<<<1, MAXBLK>>>(nblk, N);
    scanC_kernel<<<nblk, SCAN_TPB>>>(N);
    scatter_kernel<<<(E + tpb - 1) / tpb, tpb>>>(ei, E, N);

    int wblocks = (N + 7) / 8;                 // 8 warps / 256-thread block
    mlp1_kernel<<<wblocks, tpb>>>(x, W1, b1, N);
    mlp2_kernel<<<wblocks, tpb>>>(W2, b2, N);

    // steps 0..8 normal; step 9 (reads B) fuses the decode
    for (int t = 0; t < KSTEPS - 1; t++) {
        if ((t & 1) == 0) prop_kernel<1, 0><<<wblocks, tpb>>>(Wf, bf, out, N);
        else              prop_kernel<0, 0><<<wblocks, tpb>>>(Wf, bf, out, N);
    }
    prop_kernel<0, 1><<<wblocks, tpb>>>(Wf, bf, out, N);
}